// round 2
// baseline (speedup 1.0000x reference)
#include <cuda_runtime.h>

#define FULLMASK 0xFFFFFFFFu

// per-batch (loss + kld) partials
__device__ float g_partial[4096];

// transition enum: M2M=0, M2I=1, M2D=2, I2M=3, I2I=4, D2M=5, D2D=6
// shapes: x (4096,128) int32 | a (4096,65,7) f32 | e (4096,64,4) f32 | mus/logvars (4096,16)

__global__ void __launch_bounds__(256) phmm_fwd_kernel(
    const int* __restrict__ xg, const float* __restrict__ ag,
    const float* __restrict__ eg, const float* __restrict__ mug,
    const float* __restrict__ lvg)
{
    const int lane = threadIdx.x & 31;
    const int warp = threadIdx.x >> 5;
    const int b = (blockIdx.x << 3) + warp;

    const float* ab = ag + b * 455;          // 65*7
    const float* ebp = eg + (b << 8);        // 64*4

    // lane t owns states kA=2t+1 (slot A) and kB=2t+2 (slot B).
    // D-chain entering state k uses transition row k-1: rows 2t (lo) and 2t+1 (hi).
    const int r0 = lane * 2, r1 = r0 + 1, r2 = r0 + 2;

    const float M2D_lo = __expf(ab[r0 * 7 + 2]);
    const float D2D_lo = __expf(ab[r0 * 7 + 6]);

    const float tM2M_A = __expf(ab[r1 * 7 + 0]);
    const float tM2I_A = 0.25f * __expf(ab[r1 * 7 + 1]);   // fold q = exp(LOG_Q)
    const float M2D_hi = __expf(ab[r1 * 7 + 2]);
    const float tI2M_A = __expf(ab[r1 * 7 + 3]);
    const float tI2I_A = 0.25f * __expf(ab[r1 * 7 + 4]);
    const float tD2M_A = __expf(ab[r1 * 7 + 5]);
    const float D2D_hi = __expf(ab[r1 * 7 + 6]);

    const float tM2M_B = __expf(ab[r2 * 7 + 0]);
    const float tM2I_B = 0.25f * __expf(ab[r2 * 7 + 1]);
    const float tI2M_B = __expf(ab[r2 * 7 + 3]);
    const float tI2I_B = 0.25f * __expf(ab[r2 * 7 + 4]);
    const float tD2M_B = __expf(ab[r2 * 7 + 5]);

    // state-0 scalars (replicated on all lanes); fD[0]==0 so D2M row0 unused
    const float sM2M0 = __expf(ab[0]);
    const float sM2I0 = 0.25f * __expf(ab[1]);
    const float sI2M0 = __expf(ab[3]);
    const float sI2I0 = 0.25f * __expf(ab[4]);

    // emissions: slot A uses e-row 2t (feeds fM_new[2t+1]), slot B uses e-row 2t+1
    float4 e4a = __ldg((const float4*)(ebp + lane * 8));
    float4 e4b = __ldg((const float4*)(ebp + lane * 8 + 4));
    const float eA0 = __expf(e4a.x), eA1 = __expf(e4a.y), eA2 = __expf(e4a.z), eA3 = __expf(e4a.w);
    const float eB0 = __expf(e4b.x), eB1 = __expf(e4b.y), eB2 = __expf(e4b.z), eB3 = __expf(e4b.w);

    const int* xb = xg + (b << 7);
    const int xs0 = xb[lane], xs1 = xb[lane + 32], xs2 = xb[lane + 64], xs3 = xb[lane + 96];

    // Precompute the loop-invariant A-side of the Kogge-Stone scan over the
    // D-chain (prefix products of D2D). Ak_d = lane's accumulated A at ENTRY of
    // scan step d — the per-step B multiplier.
    float Ak0, Ak1, Ak2, Ak3, Ak4;
    {
        float Ac = D2D_lo * D2D_hi;
        Ak0 = Ac;
        float Au = __shfl_up_sync(FULLMASK, Ac, 1);  if (lane >= 1)  Ac *= Au;
        Ak1 = Ac;
        Au = __shfl_up_sync(FULLMASK, Ac, 2);        if (lane >= 2)  Ac *= Au;
        Ak2 = Ac;
        Au = __shfl_up_sync(FULLMASK, Ac, 4);        if (lane >= 4)  Ac *= Au;
        Ak3 = Ac;
        Au = __shfl_up_sync(FULLMASK, Ac, 8);        if (lane >= 8)  Ac *= Au;
        Ak4 = Ac;
    }

    // linear-space state (scaled); C = accumulated log-scale
    float fM_A = 0.f, fM_B = 0.f, fI_A = 0.f, fI_B = 0.f;
    float fM0 = 1.f, fI0 = 0.f, C = 0.f;
    float fD_A, fD_B;

    // ---- initial D chain (uses init fM: fM0=1, slots 0) ----
    {
        float fMup = __shfl_up_sync(FULLMASK, fM_B, 1);
        if (lane == 0) fMup = fM0;
        float B_A = M2D_lo * fMup;
        float B_B = M2D_hi * fM_A;
        float Bc = fmaf(D2D_hi, B_A, B_B);
        float Bu;
        Bu = __shfl_up_sync(FULLMASK, Bc, 1);  if (lane >= 1)  Bc = fmaf(Ak0, Bu, Bc);
        Bu = __shfl_up_sync(FULLMASK, Bc, 2);  if (lane >= 2)  Bc = fmaf(Ak1, Bu, Bc);
        Bu = __shfl_up_sync(FULLMASK, Bc, 4);  if (lane >= 4)  Bc = fmaf(Ak2, Bu, Bc);
        Bu = __shfl_up_sync(FULLMASK, Bc, 8);  if (lane >= 8)  Bc = fmaf(Ak3, Bu, Bc);
        Bu = __shfl_up_sync(FULLMASK, Bc, 16); if (lane >= 16) Bc = fmaf(Ak4, Bu, Bc);
        float fDp = __shfl_up_sync(FULLMASK, Bc, 1);
        if (lane == 0) fDp = 0.f;
        fD_A = fmaf(D2D_lo, fDp, B_A);
        fD_B = Bc;
    }

    // ---- main loop over L=128 symbols ----
    #pragma unroll
    for (int j = 0; j < 4; ++j) {
        const int xr = (j == 0) ? xs0 : (j == 1) ? xs1 : (j == 2) ? xs2 : xs3;
        for (int l2 = 0; l2 < 32; ++l2) {
            const int xl = __shfl_sync(FULLMASK, xr, l2);
            const bool s0 = (xl & 1) != 0;
            const bool s1 = (xl & 2) != 0;
            const float eselA = s1 ? (s0 ? eA3 : eA2) : (s0 ? eA1 : eA0);
            const float eselB = s1 ? (s0 ? eB3 : eB2) : (s0 ? eB1 : eB0);

            // prev[k] = M2M*fM + I2M*fI + D2M*fD at each owned state
            float prevA = fmaf(tM2M_A, fM_A, fmaf(tI2M_A, fI_A, tD2M_A * fD_A));
            float prevB = fmaf(tM2M_B, fM_B, fmaf(tI2M_B, fI_B, tD2M_B * fD_B));
            float prevUp = __shfl_up_sync(FULLMASK, prevB, 1);      // prev[2t]
            if (lane == 0) prevUp = fmaf(sM2M0, fM0, sI2M0 * fI0);  // prev[0]

            // fM_new[k] = e[k-1][x] * prev[k-1]
            float fMnA = eselA * prevUp;   // state 2t+1
            float fMnB = eselB * prevA;    // state 2t+2

            // fI_new[k] = q*(M2I*fM + I2I*fI)   (q folded)
            float fInA = fmaf(tM2I_A, fM_A, tI2I_A * fI_A);
            float fInB = fmaf(tM2I_B, fM_B, tI2I_B * fI_B);
            float fI0n = fmaf(sM2I0, fM0, sI2I0 * fI0);

            // D chain on fM_new: fD[k] = D2D[k-1]*fD[k-1] + M2D[k-1]*fM_new[k-1]
            float fMup = __shfl_up_sync(FULLMASK, fMnB, 1);   // fM_new[2t]
            if (lane == 0) fMup = 0.f;                        // fM_new[0] = 0
            float B_A = M2D_lo * fMup;
            float B_B = M2D_hi * fMnA;
            float Bc = fmaf(D2D_hi, B_A, B_B);
            float Bu;
            Bu = __shfl_up_sync(FULLMASK, Bc, 1);  if (lane >= 1)  Bc = fmaf(Ak0, Bu, Bc);
            Bu = __shfl_up_sync(FULLMASK, Bc, 2);  if (lane >= 2)  Bc = fmaf(Ak1, Bu, Bc);
            Bu = __shfl_up_sync(FULLMASK, Bc, 4);  if (lane >= 4)  Bc = fmaf(Ak2, Bu, Bc);
            Bu = __shfl_up_sync(FULLMASK, Bc, 8);  if (lane >= 8)  Bc = fmaf(Ak3, Bu, Bc);
            Bu = __shfl_up_sync(FULLMASK, Bc, 16); if (lane >= 16) Bc = fmaf(Ak4, Bu, Bc);
            float fDp = __shfl_up_sync(FULLMASK, Bc, 1);
            if (lane == 0) fDp = 0.f;
            float fDnA = fmaf(D2D_lo, fDp, B_A);
            float fDnB = Bc;

            // per-step rescale (keeps one-step D-chain blowup inside float range)
            float m = fmaxf(fmaxf(fmaxf(fMnA, fMnB), fmaxf(fInA, fInB)),
                            fmaxf(fmaxf(fDnA, fDnB), fI0n));
            m = fmaxf(m, __shfl_xor_sync(FULLMASK, m, 16));
            m = fmaxf(m, __shfl_xor_sync(FULLMASK, m, 8));
            m = fmaxf(m, __shfl_xor_sync(FULLMASK, m, 4));
            m = fmaxf(m, __shfl_xor_sync(FULLMASK, m, 2));
            m = fmaxf(m, __shfl_xor_sync(FULLMASK, m, 1));
            float r = __frcp_rn(m);
            C -= __logf(r);
            fM_A = fMnA * r; fM_B = fMnB * r;
            fI_A = fInA * r; fI_B = fInB * r;
            fD_A = fDnA * r; fD_B = fDnB * r;
            fI0 = fI0n * r;
            fM0 = 0.f;
        }
    }

    // final = fM[64]*M2M[64] + fI[64]*I2M[64] + fD[64]*D2M[64]  (lane 31, slot B)
    float fin = fmaf(tM2M_B, fM_B, fmaf(tI2M_B, fI_B, tD2M_B * fD_B));
    float loss = -(__logf(fin) + C);
    loss = __shfl_sync(FULLMASK, loss, 31);

    // KLD: -0.5 * sum_e (1 + lv - mu^2 - exp(lv)), E = 16
    float kt = 0.f;
    if (lane < 16) {
        float mu = mug[b * 16 + lane];
        float lv = lvg[b * 16 + lane];
        kt = 1.f + lv - mu * mu - __expf(lv);
    }
    kt += __shfl_xor_sync(FULLMASK, kt, 16);
    kt += __shfl_xor_sync(FULLMASK, kt, 8);
    kt += __shfl_xor_sync(FULLMASK, kt, 4);
    kt += __shfl_xor_sync(FULLMASK, kt, 2);
    kt += __shfl_xor_sync(FULLMASK, kt, 1);

    if (lane == 0) g_partial[b] = loss - 0.5f * kt;
}

__global__ void reduce_kernel(float* __restrict__ out)
{
    __shared__ float sh[1024];
    const int t = threadIdx.x;
    sh[t] = g_partial[t] + g_partial[t + 1024] + g_partial[t + 2048] + g_partial[t + 3072];
    __syncthreads();
    for (int s = 512; s > 0; s >>= 1) {
        if (t < s) sh[t] += sh[t + s];
        __syncthreads();
    }
    if (t == 0) out[0] = sh[0] * (1.0f / 4096.0f);
}

extern "C" void kernel_launch(void* const* d_in, const int* in_sizes, int n_in,
                              void* d_out, int out_size)
{
    const int*   x   = (const int*)d_in[0];
    const float* a   = (const float*)d_in[1];
    const float* e   = (const float*)d_in[2];
    const float* mus = (const float*)d_in[3];
    const float* lvs = (const float*)d_in[4];

    phmm_fwd_kernel<<<512, 256>>>(x, a, e, mus, lvs);
    reduce_kernel<<<1, 1024>>>((float*)d_out);
}

// round 3
// speedup vs baseline: 1.6764x; 1.6764x over previous
#include <cuda_runtime.h>

#define FULLMASK 0xFFFFFFFFu
typedef unsigned long long u64;

__device__ float g_partial[4096];
__device__ int g_count = 0;

// ---- f32x2 packed helpers (sm_100+) ----
static __device__ __forceinline__ u64 pk(float lo, float hi) {
    u64 r; asm("mov.b64 %0, {%1, %2};" : "=l"(r) : "f"(lo), "f"(hi)); return r;
}
static __device__ __forceinline__ float f2lo(u64 v) {
    float a, b; asm("mov.b64 {%0, %1}, %2;" : "=f"(a), "=f"(b) : "l"(v)); return a;
}
static __device__ __forceinline__ float f2hi(u64 v) {
    float a, b; asm("mov.b64 {%0, %1}, %2;" : "=f"(a), "=f"(b) : "l"(v)); return b;
}
static __device__ __forceinline__ u64 fma2(u64 a, u64 b, u64 c) {
    u64 d; asm("fma.rn.f32x2 %0, %1, %2, %3;" : "=l"(d) : "l"(a), "l"(b), "l"(c)); return d;
}
static __device__ __forceinline__ u64 mul2(u64 a, u64 b) {
    u64 d; asm("mul.rn.f32x2 %0, %1, %2;" : "=l"(d) : "l"(a), "l"(b)); return d;
}

// One HMM step. Lane t owns states 2t+1 (lo/A) and 2t+2 (hi/B).
#define PHMM_STEP(XL) do {                                                      \
    const int xl = (XL);                                                        \
    u64 esel = (xl & 2) ? ((xl & 1) ? e3 : e2) : ((xl & 1) ? e1 : e0);          \
    u64 prev2 = fma2(tM2M2, fM2, fma2(tI2M2, fI2, mul2(tD2M2, fD2)));           \
    float prevUp = __shfl_up_sync(FULLMASK, f2hi(prev2), 1);                    \
    if (lane == 0) prevUp = fmaf(sM2M0, fM0, sI2M0 * fI0);                      \
    u64 fMn2 = mul2(esel, pk(prevUp, f2lo(prev2)));                             \
    u64 fIn2 = fma2(tM2I2, fM2, mul2(tI2I2, fI2));                              \
    float fI0n = fmaf(sM2I0, fM0, sI2I0 * fI0);                                 \
    float fMup = __shfl_up_sync(FULLMASK, f2hi(fMn2), 1);                       \
    if (lane == 0) fMup = 0.f;                                                  \
    u64 Bv = mul2(M2D2, pk(fMup, f2lo(fMn2)));                                  \
    float B_A = f2lo(Bv);                                                       \
    float Bc = fmaf(D2D_hi, B_A, f2hi(Bv));                                     \
    float Bu;                                                                   \
    Bu = __shfl_up_sync(FULLMASK, Bc, 1);  if (lane >= 1)  Bc = fmaf(Ak0, Bu, Bc); \
    Bu = __shfl_up_sync(FULLMASK, Bc, 2);  if (lane >= 2)  Bc = fmaf(Ak1, Bu, Bc); \
    Bu = __shfl_up_sync(FULLMASK, Bc, 4);  if (lane >= 4)  Bc = fmaf(Ak2, Bu, Bc); \
    Bu = __shfl_up_sync(FULLMASK, Bc, 8);  if (lane >= 8)  Bc = fmaf(Ak3, Bu, Bc); \
    Bu = __shfl_up_sync(FULLMASK, Bc, 16); if (lane >= 16) Bc = fmaf(Ak4, Bu, Bc); \
    float fDp = __shfl_up_sync(FULLMASK, Bc, 1);                                \
    if (lane == 0) fDp = 0.f;                                                   \
    fM2 = fMn2; fI2 = fIn2; fI0 = fI0n; fM0 = 0.f;                              \
    fD2 = pk(fmaf(D2D_lo, fDp, B_A), Bc);                                       \
} while (0)

// Renormalize by 2^-floor(log2(max)); accumulate integer exponent in Ci.
#define PHMM_RESCALE do {                                                       \
    float m = fmaxf(fmaxf(f2lo(fM2), f2hi(fM2)), fmaxf(f2lo(fI2), f2hi(fI2))); \
    m = fmaxf(m, fmaxf(f2lo(fD2), f2hi(fD2)));                                  \
    m = fmaxf(m, fI0);                                                          \
    m = fmaxf(m, __shfl_xor_sync(FULLMASK, m, 16));                             \
    m = fmaxf(m, __shfl_xor_sync(FULLMASK, m, 8));                              \
    m = fmaxf(m, __shfl_xor_sync(FULLMASK, m, 4));                              \
    m = fmaxf(m, __shfl_xor_sync(FULLMASK, m, 2));                              \
    m = fmaxf(m, __shfl_xor_sync(FULLMASK, m, 1));                              \
    int be = __float_as_int(m) >> 23;                                           \
    Ci += be - 127;                                                             \
    float r = __int_as_float((254 - be) << 23);                                 \
    u64 r2 = pk(r, r);                                                          \
    fM2 = mul2(fM2, r2); fI2 = mul2(fI2, r2); fD2 = mul2(fD2, r2); fI0 *= r;    \
} while (0)

__global__ void __launch_bounds__(256) phmm_fused_kernel(
    const int* __restrict__ xg, const float* __restrict__ ag,
    const float* __restrict__ eg, const float* __restrict__ mug,
    const float* __restrict__ lvg, float* __restrict__ outp)
{
    const int lane = threadIdx.x & 31;
    const int warp = threadIdx.x >> 5;
    const int b = (blockIdx.x << 3) + warp;

    const float* ab = ag + b * 455;   // (65,7)
    const float* ebp = eg + (b << 8); // (64,4)

    const int r0 = lane * 2, r1 = r0 + 1, r2 = r0 + 2;

    const float M2D_lo = __expf(ab[r0 * 7 + 2]);
    const float D2D_lo = __expf(ab[r0 * 7 + 6]);
    const float M2D_hi = __expf(ab[r1 * 7 + 2]);
    const float D2D_hi = __expf(ab[r1 * 7 + 6]);
    const u64 M2D2 = pk(M2D_lo, M2D_hi);

    const u64 tM2M2 = pk(__expf(ab[r1 * 7 + 0]), __expf(ab[r2 * 7 + 0]));
    const u64 tM2I2 = pk(0.25f * __expf(ab[r1 * 7 + 1]), 0.25f * __expf(ab[r2 * 7 + 1]));
    const u64 tI2M2 = pk(__expf(ab[r1 * 7 + 3]), __expf(ab[r2 * 7 + 3]));
    const u64 tI2I2 = pk(0.25f * __expf(ab[r1 * 7 + 4]), 0.25f * __expf(ab[r2 * 7 + 4]));
    const u64 tD2M2 = pk(__expf(ab[r1 * 7 + 5]), __expf(ab[r2 * 7 + 5]));

    const float sM2M0 = __expf(ab[0]);
    const float sM2I0 = 0.25f * __expf(ab[1]);
    const float sI2M0 = __expf(ab[3]);
    const float sI2I0 = 0.25f * __expf(ab[4]);

    // emissions: slot A = e-row 2t, slot B = e-row 2t+1; packed per symbol
    float4 e4a = __ldg((const float4*)(ebp + lane * 8));
    float4 e4b = __ldg((const float4*)(ebp + lane * 8 + 4));
    const u64 e0 = pk(__expf(e4a.x), __expf(e4b.x));
    const u64 e1 = pk(__expf(e4a.y), __expf(e4b.y));
    const u64 e2 = pk(__expf(e4a.z), __expf(e4b.z));
    const u64 e3 = pk(__expf(e4a.w), __expf(e4b.w));

    // ---- pack symbols: lane t loads x[4t..4t+3]; 2 butterfly rounds ->
    // lanes 4k..4k+3 all hold word k = symbols [16k..16k+15], 2 bits each ----
    int word;
    {
        const int4 xv = *(const int4*)(xg + (b << 7) + (lane << 2));
        int c8 = xv.x | (xv.y << 2) | (xv.z << 4) | (xv.w << 6);
        int o1 = __shfl_xor_sync(FULLMASK, c8, 1);
        int p16 = (lane & 1) ? ((c8 << 8) | o1) : (c8 | (o1 << 8));
        int o2 = __shfl_xor_sync(FULLMASK, p16, 2);
        word = (lane & 2) ? ((p16 << 16) | o2) : (p16 | (o2 << 16));
    }

    // Loop-invariant Kogge-Stone A-side (D2D prefix products)
    float Ak0, Ak1, Ak2, Ak3, Ak4;
    {
        float Ac = D2D_lo * D2D_hi;
        Ak0 = Ac;
        float Au = __shfl_up_sync(FULLMASK, Ac, 1); if (lane >= 1) Ac *= Au;
        Ak1 = Ac;
        Au = __shfl_up_sync(FULLMASK, Ac, 2);       if (lane >= 2) Ac *= Au;
        Ak2 = Ac;
        Au = __shfl_up_sync(FULLMASK, Ac, 4);       if (lane >= 4) Ac *= Au;
        Ak3 = Ac;
        Au = __shfl_up_sync(FULLMASK, Ac, 8);       if (lane >= 8) Ac *= Au;
        Ak4 = Ac;
    }

    // state (scaled linear space); Ci accumulates log2-scale as integer
    u64 fM2 = pk(0.f, 0.f), fI2 = pk(0.f, 0.f), fD2;
    float fM0 = 1.f, fI0 = 0.f;
    int Ci = 0;

    // initial D chain from init fM (fM0=1, rest 0)
    {
        float fMup = (lane == 0) ? 1.f : 0.f;
        u64 Bv = mul2(M2D2, pk(fMup, 0.f));
        float B_A = f2lo(Bv);
        float Bc = fmaf(D2D_hi, B_A, f2hi(Bv));
        float Bu;
        Bu = __shfl_up_sync(FULLMASK, Bc, 1);  if (lane >= 1)  Bc = fmaf(Ak0, Bu, Bc);
        Bu = __shfl_up_sync(FULLMASK, Bc, 2);  if (lane >= 2)  Bc = fmaf(Ak1, Bu, Bc);
        Bu = __shfl_up_sync(FULLMASK, Bc, 4);  if (lane >= 4)  Bc = fmaf(Ak2, Bu, Bc);
        Bu = __shfl_up_sync(FULLMASK, Bc, 8);  if (lane >= 8)  Bc = fmaf(Ak3, Bu, Bc);
        Bu = __shfl_up_sync(FULLMASK, Bc, 16); if (lane >= 16) Bc = fmaf(Ak4, Bu, Bc);
        float fDp = __shfl_up_sync(FULLMASK, Bc, 1);
        if (lane == 0) fDp = 0.f;
        fD2 = pk(fmaf(D2D_lo, fDp, B_A), Bc);
    }

    // ---- main loop: 8 words x 16 symbols; rescale every 8 steps ----
    #pragma unroll 1
    for (int wi = 0; wi < 8; ++wi) {
        int w = __shfl_sync(FULLMASK, word, wi << 2);
        #pragma unroll
        for (int i = 0; i < 8; ++i) { PHMM_STEP(w & 3); w >>= 2; }
        PHMM_RESCALE;
        #pragma unroll
        for (int i = 0; i < 8; ++i) { PHMM_STEP(w & 3); w >>= 2; }
        PHMM_RESCALE;
    }

    // final = fM[64]*M2M + fI[64]*I2M + fD[64]*D2M : lane 31, hi slot
    u64 fin2 = fma2(tM2M2, fM2, fma2(tI2M2, fI2, mul2(tD2M2, fD2)));
    float loss = -(__logf(f2hi(fin2)) + (float)Ci * 0.6931471805599453f);
    loss = __shfl_sync(FULLMASK, loss, 31);

    // KLD
    float kt = 0.f;
    if (lane < 16) {
        float mu = mug[b * 16 + lane];
        float lv = lvg[b * 16 + lane];
        kt = 1.f + lv - mu * mu - __expf(lv);
    }
    kt += __shfl_xor_sync(FULLMASK, kt, 16);
    kt += __shfl_xor_sync(FULLMASK, kt, 8);
    kt += __shfl_xor_sync(FULLMASK, kt, 4);
    kt += __shfl_xor_sync(FULLMASK, kt, 2);
    kt += __shfl_xor_sync(FULLMASK, kt, 1);

    if (lane == 0) g_partial[b] = loss - 0.5f * kt;

    // ---- fused deterministic final reduction (last-block pattern) ----
    __shared__ float ws[8];
    __shared__ int isLast;
    __syncthreads();
    if (threadIdx.x == 0) {
        __threadfence();
        isLast = (atomicAdd(&g_count, 1) == (int)gridDim.x - 1);
    }
    __syncthreads();
    if (isLast) {
        const float4* gp = (const float4*)g_partial;
        float s = 0.f;
        #pragma unroll
        for (int i = 0; i < 4; ++i) {
            float4 v = gp[threadIdx.x + (i << 8)];
            s += (v.x + v.y) + (v.z + v.w);
        }
        s += __shfl_xor_sync(FULLMASK, s, 16);
        s += __shfl_xor_sync(FULLMASK, s, 8);
        s += __shfl_xor_sync(FULLMASK, s, 4);
        s += __shfl_xor_sync(FULLMASK, s, 2);
        s += __shfl_xor_sync(FULLMASK, s, 1);
        if (lane == 0) ws[warp] = s;
        __syncthreads();
        if (threadIdx.x == 0) {
            float t = 0.f;
            #pragma unroll
            for (int i = 0; i < 8; ++i) t += ws[i];
            *outp = t * (1.0f / 4096.0f);
            g_count = 0;   // reset for next graph replay
        }
    }
}

extern "C" void kernel_launch(void* const* d_in, const int* in_sizes, int n_in,
                              void* d_out, int out_size)
{
    const int*   x   = (const int*)d_in[0];
    const float* a   = (const float*)d_in[1];
    const float* e   = (const float*)d_in[2];
    const float* mus = (const float*)d_in[3];
    const float* lvs = (const float*)d_in[4];

    phmm_fused_kernel<<<512, 256>>>(x, a, e, mus, lvs, (float*)d_out);
}

// round 8
// speedup vs baseline: 1.8732x; 1.1174x over previous
#include <cuda_runtime.h>

#define FULLMASK 0xFFFFFFFFu
typedef unsigned long long u64;

__device__ float g_partial[4096];
__device__ int g_count = 0;

// ---- f32x2 packed helpers (sm_100+) ----
static __device__ __forceinline__ u64 pk(float lo, float hi) {
    u64 r; asm("mov.b64 %0, {%1, %2};" : "=l"(r) : "f"(lo), "f"(hi)); return r;
}
static __device__ __forceinline__ float f2lo(u64 v) {
    float a, b; asm("mov.b64 {%0, %1}, %2;" : "=f"(a), "=f"(b) : "l"(v)); return a;
}
static __device__ __forceinline__ float f2hi(u64 v) {
    float a, b; asm("mov.b64 {%0, %1}, %2;" : "=f"(a), "=f"(b) : "l"(v)); return b;
}
static __device__ __forceinline__ u64 fma2(u64 a, u64 b, u64 c) {
    u64 d; asm("fma.rn.f32x2 %0, %1, %2, %3;" : "=l"(d) : "l"(a), "l"(b), "l"(c)); return d;
}
static __device__ __forceinline__ u64 mul2(u64 a, u64 b) {
    u64 d; asm("mul.rn.f32x2 %0, %1, %2;" : "=l"(d) : "l"(a), "l"(b)); return d;
}

// One step. Half-warp per batch element; lane sub owns states 4s+1..4s+4.
#define PHMM_STEP(XL) do {                                                       \
    const int xl = (XL);                                                         \
    const bool s0 = (xl & 1) != 0, s1 = (xl & 2) != 0;                           \
    u64 eselP = s1 ? (s0 ? eP3 : eP2) : (s0 ? eP1 : eP0);                        \
    u64 eselQ = s1 ? (s0 ? eQ3 : eQ2) : (s0 ? eQ1 : eQ0);                        \
    float eselX = s1 ? (s0 ? eX3 : eX2) : (s0 ? eX1 : eX0);                      \
    u64 prevP = fma2(tM2M_P, fM_P, fma2(tI2M_P, fI_P, mul2(tD2M_P, fD_P)));      \
    u64 prevQ = fma2(tM2M_Q, fM_Q, fma2(tI2M_Q, fI_Q, mul2(tD2M_Q, fD_Q)));      \
    float pUpLo = __shfl_up_sync(FULLMASK, f2lo(prevQ), 1, 16);                  \
    float pUpHi = __shfl_up_sync(FULLMASK, f2hi(prevQ), 1, 16);                  \
    if (sub == 0) pUpHi = fmaf(sM2M0, fM0, sI2M0 * fI0);                         \
    u64 fMnP = mul2(eselP, pk(pUpHi, f2lo(prevP)));                              \
    u64 fMnQ = mul2(eselQ, pk(f2hi(prevP), f2lo(prevQ)));                        \
    float fMnX = eselX * pUpLo; /* eX==0 at sub 0 -> fMn[0]=0 */                 \
    u64 fInP = fma2(tM2I_P, fM_P, mul2(tI2I_P, fI_P));                           \
    u64 fInQ = fma2(tM2I_Q, fM_Q, mul2(tI2I_Q, fI_Q));                           \
    float fI0n = fmaf(sM2I0, fM0, sI2I0 * fI0);                                  \
    float b1 = m0 * fMnX;                                                        \
    float b2 = fmaf(d1, b1, m1 * f2lo(fMnP));                                    \
    float b3 = fmaf(d2, b2, m2 * f2hi(fMnP));                                    \
    float Bc = fmaf(d3, b3, m3 * f2lo(fMnQ));                                    \
    float Bu;                                                                    \
    Bu = __shfl_up_sync(FULLMASK, Bc, 1, 16); if (sub >= 1) Bc = fmaf(Ak0, Bu, Bc); \
    Bu = __shfl_up_sync(FULLMASK, Bc, 2, 16); if (sub >= 2) Bc = fmaf(Ak1, Bu, Bc); \
    Bu = __shfl_up_sync(FULLMASK, Bc, 4, 16); if (sub >= 4) Bc = fmaf(Ak2, Bu, Bc); \
    Bu = __shfl_up_sync(FULLMASK, Bc, 8, 16); if (sub >= 8) Bc = fmaf(Ak3, Bu, Bc); \
    float fDp = __shfl_up_sync(FULLMASK, Bc, 1, 16);                             \
    if (sub == 0) fDp = 0.f;                                                     \
    fM_P = fMnP; fM_Q = fMnQ; fI_P = fInP; fI_Q = fInQ;                          \
    fI0 = fI0n; fM0 = 0.f;                                                       \
    fD_P = pk(fmaf(A1, fDp, b1), fmaf(A2, fDp, b2));                             \
    fD_Q = pk(fmaf(A3, fDp, b3), Bc);                                            \
} while (0)

#define PHMM_RESCALE do {                                                        \
    float m = fmaxf(fmaxf(f2lo(fM_P), f2hi(fM_P)), fmaxf(f2lo(fM_Q), f2hi(fM_Q))); \
    m = fmaxf(m, fmaxf(fmaxf(f2lo(fI_P), f2hi(fI_P)), fmaxf(f2lo(fI_Q), f2hi(fI_Q)))); \
    m = fmaxf(m, fmaxf(fmaxf(f2lo(fD_P), f2hi(fD_P)), fmaxf(f2lo(fD_Q), f2hi(fD_Q)))); \
    m = fmaxf(m, fI0);                                                           \
    m = fmaxf(m, __shfl_xor_sync(FULLMASK, m, 8, 16));                           \
    m = fmaxf(m, __shfl_xor_sync(FULLMASK, m, 4, 16));                           \
    m = fmaxf(m, __shfl_xor_sync(FULLMASK, m, 2, 16));                           \
    m = fmaxf(m, __shfl_xor_sync(FULLMASK, m, 1, 16));                           \
    int be = __float_as_int(m) >> 23;                                            \
    Ci += be - 127;                                                              \
    float r = __int_as_float((254 - be) << 23);                                  \
    u64 r2 = pk(r, r);                                                           \
    fM_P = mul2(fM_P, r2); fM_Q = mul2(fM_Q, r2);                                \
    fI_P = mul2(fI_P, r2); fI_Q = mul2(fI_Q, r2);                                \
    fD_P = mul2(fD_P, r2); fD_Q = mul2(fD_Q, r2);                                \
    fI0 *= r;                                                                    \
} while (0)

__global__ void __launch_bounds__(256) phmm_fused_kernel(
    const int* __restrict__ xg, const float* __restrict__ ag,
    const float* __restrict__ eg, const float* __restrict__ mug,
    const float* __restrict__ lvg, float* __restrict__ outp)
{
    const int lane = threadIdx.x & 31;
    const int warp = threadIdx.x >> 5;
    const int sub  = lane & 15;          // lane within half-warp
    const int half = lane >> 4;
    const int b = (blockIdx.x << 4) + (warp << 1) + half;

    const float* ab  = ag + b * 455;     // (65,7)
    const float* ebp = eg + (b << 8);    // (64,4)

    // a-rows needed: R0=4s (M2D,D2D), R1..R3 (all), R4 (M2M,M2I,I2M,I2I,D2M)
    const int R0 = sub << 2;
    const float* p0 = ab + R0 * 7;

    const float m0 = __expf(p0[2]),      d0 = __expf(p0[6]);
    const float m1 = __expf(p0[7 + 2]),  d1 = __expf(p0[7 + 6]);
    const float m2 = __expf(p0[14 + 2]), d2 = __expf(p0[14 + 6]);
    const float m3 = __expf(p0[21 + 2]), d3 = __expf(p0[21 + 6]);

    const u64 tM2M_P = pk(__expf(p0[7 + 0]), __expf(p0[14 + 0]));
    const u64 tM2I_P = pk(0.25f * __expf(p0[7 + 1]), 0.25f * __expf(p0[14 + 1]));
    const u64 tI2M_P = pk(__expf(p0[7 + 3]), __expf(p0[14 + 3]));
    const u64 tI2I_P = pk(0.25f * __expf(p0[7 + 4]), 0.25f * __expf(p0[14 + 4]));
    const u64 tD2M_P = pk(__expf(p0[7 + 5]), __expf(p0[14 + 5]));

    const u64 tM2M_Q = pk(__expf(p0[21 + 0]), __expf(p0[28 + 0]));
    const u64 tM2I_Q = pk(0.25f * __expf(p0[21 + 1]), 0.25f * __expf(p0[28 + 1]));
    const u64 tI2M_Q = pk(__expf(p0[21 + 3]), __expf(p0[28 + 3]));
    const u64 tI2I_Q = pk(0.25f * __expf(p0[21 + 4]), 0.25f * __expf(p0[28 + 4]));
    const u64 tD2M_Q = pk(__expf(p0[21 + 5]), __expf(p0[28 + 5]));

    // state-0 scalars
    const float sM2M0 = __expf(ab[0]);
    const float sM2I0 = 0.25f * __expf(ab[1]);
    const float sI2M0 = __expf(ab[3]);
    const float sI2I0 = 0.25f * __expf(ab[4]);

    // A-prefixes of the in-lane D-chain (loop-invariant)
    const float A1 = d0, A2 = d1 * d0, A3 = d2 * A2, Alane = d3 * A3;

    // emissions: rows 4s..4s+3; eX = row 4s-1 from neighbor via shfl
    float4 er0 = __ldg((const float4*)(ebp + (R0 << 2)));
    float4 er1 = __ldg((const float4*)(ebp + (R0 << 2) + 4));
    float4 er2 = __ldg((const float4*)(ebp + (R0 << 2) + 8));
    float4 er3 = __ldg((const float4*)(ebp + (R0 << 2) + 12));
    float x30 = __expf(er3.x), x31 = __expf(er3.y), x32 = __expf(er3.z), x33 = __expf(er3.w);
    const u64 eP0 = pk(__expf(er0.x), __expf(er1.x));
    const u64 eP1 = pk(__expf(er0.y), __expf(er1.y));
    const u64 eP2 = pk(__expf(er0.z), __expf(er1.z));
    const u64 eP3 = pk(__expf(er0.w), __expf(er1.w));
    const u64 eQ0 = pk(__expf(er2.x), x30);
    const u64 eQ1 = pk(__expf(er2.y), x31);
    const u64 eQ2 = pk(__expf(er2.z), x32);
    const u64 eQ3 = pk(__expf(er2.w), x33);
    float eX0 = __shfl_up_sync(FULLMASK, x30, 1, 16);
    float eX1 = __shfl_up_sync(FULLMASK, x31, 1, 16);
    float eX2 = __shfl_up_sync(FULLMASK, x32, 1, 16);
    float eX3 = __shfl_up_sync(FULLMASK, x33, 1, 16);
    if (sub == 0) { eX0 = 0.f; eX1 = 0.f; eX2 = 0.f; eX3 = 0.f; }

    // ---- pack symbols: lane sub loads x[8*sub..8*sub+7] (2 bits each = 16b),
    // one butterfly -> lanes 2m,2m+1 hold word m = symbols [16m..16m+15] ----
    int word;
    {
        const int4 xa = *(const int4*)(xg + (b << 7) + (sub << 3));
        const int4 xbv = *(const int4*)(xg + (b << 7) + (sub << 3) + 4);
        int c16 = xa.x | (xa.y << 2) | (xa.z << 4) | (xa.w << 6)
                | (xbv.x << 8) | (xbv.y << 10) | (xbv.z << 12) | (xbv.w << 14);
        int o1 = __shfl_xor_sync(FULLMASK, c16, 1, 16);
        word = (sub & 1) ? ((c16 << 16) | o1) : (c16 | (o1 << 16));
    }

    // Kogge-Stone A-side over 16 lanes (levels 1,2,4; level 8 uses Ak3)
    float Ak0, Ak1, Ak2, Ak3;
    {
        float Ac = Alane;
        Ak0 = Ac;
        float Au = __shfl_up_sync(FULLMASK, Ac, 1, 16); if (sub >= 1) Ac *= Au;
        Ak1 = Ac;
        Au = __shfl_up_sync(FULLMASK, Ac, 2, 16);       if (sub >= 2) Ac *= Au;
        Ak2 = Ac;
        Au = __shfl_up_sync(FULLMASK, Ac, 4, 16);       if (sub >= 4) Ac *= Au;
        Ak3 = Ac;
    }

    // state (scaled linear space)
    u64 fM_P = pk(0.f, 0.f), fM_Q = pk(0.f, 0.f);
    u64 fI_P = pk(0.f, 0.f), fI_Q = pk(0.f, 0.f);
    u64 fD_P, fD_Q;
    float fM0 = 1.f, fI0 = 0.f;
    int Ci = 0;

    // initial D chain: fM_init[0]=1, rest 0
    {
        float b1 = (sub == 0) ? m0 : 0.f;
        float b2 = d1 * b1;
        float b3 = d2 * b2;
        float Bc = d3 * b3;
        float Bu;
        Bu = __shfl_up_sync(FULLMASK, Bc, 1, 16); if (sub >= 1) Bc = fmaf(Ak0, Bu, Bc);
        Bu = __shfl_up_sync(FULLMASK, Bc, 2, 16); if (sub >= 2) Bc = fmaf(Ak1, Bu, Bc);
        Bu = __shfl_up_sync(FULLMASK, Bc, 4, 16); if (sub >= 4) Bc = fmaf(Ak2, Bu, Bc);
        Bu = __shfl_up_sync(FULLMASK, Bc, 8, 16); if (sub >= 8) Bc = fmaf(Ak3, Bu, Bc);
        float fDp = __shfl_up_sync(FULLMASK, Bc, 1, 16);
        if (sub == 0) fDp = 0.f;
        fD_P = pk(fmaf(A1, fDp, b1), fmaf(A2, fDp, b2));
        fD_Q = pk(fmaf(A3, fDp, b3), Bc);
    }

    // ---- main loop: 8 words x 16 symbols; rescale every 8 steps ----
    #pragma unroll 1
    for (int wi = 0; wi < 8; ++wi) {
        int w = __shfl_sync(FULLMASK, word, wi << 1, 16);
        #pragma unroll
        for (int i = 0; i < 8; ++i) { PHMM_STEP(w & 3); w >>= 2; }
        PHMM_RESCALE;
        #pragma unroll
        for (int i = 0; i < 8; ++i) { PHMM_STEP(w & 3); w >>= 2; }
        PHMM_RESCALE;
    }

    // final = fM[64]*M2M[64] + fI[64]*I2M[64] + fD[64]*D2M[64] : sub=15, hi slot
    u64 fin2 = fma2(tM2M_Q, fM_Q, fma2(tI2M_Q, fI_Q, mul2(tD2M_Q, fD_Q)));
    float loss = -(__logf(f2hi(fin2)) + (float)Ci * 0.6931471805599453f);
    loss = __shfl_sync(FULLMASK, loss, 15, 16);   // broadcast within half

    // KLD: 16 values per element, one per lane of the half
    float mu = mug[(b << 4) + sub];
    float lv = lvg[(b << 4) + sub];
    float kt = 1.f + lv - mu * mu - __expf(lv);
    kt += __shfl_xor_sync(FULLMASK, kt, 8, 16);
    kt += __shfl_xor_sync(FULLMASK, kt, 4, 16);
    kt += __shfl_xor_sync(FULLMASK, kt, 2, 16);
    kt += __shfl_xor_sync(FULLMASK, kt, 1, 16);

    if (sub == 0) g_partial[b] = loss - 0.5f * kt;

    // ---- fused deterministic final reduction (last-block pattern) ----
    __shared__ float ws[8];
    __shared__ int isLast;
    __syncthreads();
    if (threadIdx.x == 0) {
        __threadfence();
        isLast = (atomicAdd(&g_count, 1) == (int)gridDim.x - 1);
    }
    __syncthreads();
    if (isLast) {
        const float4* gp = (const float4*)g_partial;
        float s = 0.f;
        #pragma unroll
        for (int i = 0; i < 4; ++i) {
            float4 v = gp[threadIdx.x + (i << 8)];
            s += (v.x + v.y) + (v.z + v.w);
        }
        s += __shfl_xor_sync(FULLMASK, s, 16);
        s += __shfl_xor_sync(FULLMASK, s, 8);
        s += __shfl_xor_sync(FULLMASK, s, 4);
        s += __shfl_xor_sync(FULLMASK, s, 2);
        s += __shfl_xor_sync(FULLMASK, s, 1);
        if (lane == 0) ws[warp] = s;
        __syncthreads();
        if (threadIdx.x == 0) {
            float t = 0.f;
            #pragma unroll
            for (int i = 0; i < 8; ++i) t += ws[i];
            *outp = t * (1.0f / 4096.0f);
            g_count = 0;   // reset for next graph replay
        }
    }
}

extern "C" void kernel_launch(void* const* d_in, const int* in_sizes, int n_in,
                              void* d_out, int out_size)
{
    const int*   x   = (const int*)d_in[0];
    const float* a   = (const float*)d_in[1];
    const float* e   = (const float*)d_in[2];
    const float* mus = (const float*)d_in[3];
    const float* lvs = (const float*)d_in[4];

    phmm_fused_kernel<<<256, 256>>>(x, a, e, mus, lvs, (float*)d_out);
}

// round 9
// speedup vs baseline: 1.8943x; 1.0113x over previous
#include <cuda_runtime.h>

#define FULLMASK 0xFFFFFFFFu
typedef unsigned long long u64;

__device__ float g_partial[4096];
__device__ int g_count = 0;

// ---- f32x2 packed helpers (sm_100+) ----
static __device__ __forceinline__ u64 pk(float lo, float hi) {
    u64 r; asm("mov.b64 %0, {%1, %2};" : "=l"(r) : "f"(lo), "f"(hi)); return r;
}
static __device__ __forceinline__ float f2lo(u64 v) {
    float a, b; asm("mov.b64 {%0, %1}, %2;" : "=f"(a), "=f"(b) : "l"(v)); return a;
}
static __device__ __forceinline__ float f2hi(u64 v) {
    float a, b; asm("mov.b64 {%0, %1}, %2;" : "=f"(a), "=f"(b) : "l"(v)); return b;
}
static __device__ __forceinline__ u64 fma2(u64 a, u64 b, u64 c) {
    u64 d; asm("fma.rn.f32x2 %0, %1, %2, %3;" : "=l"(d) : "l"(a), "l"(b), "l"(c)); return d;
}
static __device__ __forceinline__ u64 mul2(u64 a, u64 b) {
    u64 d; asm("mul.rn.f32x2 %0, %1, %2;" : "=l"(d) : "l"(a), "l"(b)); return d;
}

// One step. Half-warp per batch element; lane sub owns states 4s+1..4s+4.
// Emissions come from the per-element smem table (1 x ld.shared.v4, issued
// early; latency hidden under the prev-chain + shuffles).
#define PHMM_STEP(XL) do {                                                       \
    const int xl = (XL);                                                         \
    const float4 ev = *(const float4*)(myt + ((xl) << 6) + (sub << 2));          \
    const bool s0 = (xl & 1) != 0, s1 = (xl & 2) != 0;                           \
    float eselX = s1 ? (s0 ? eX3 : eX2) : (s0 ? eX1 : eX0);                      \
    u64 prevP = fma2(tM2M_P, fM_P, fma2(tI2M_P, fI_P, mul2(tD2M_P, fD_P)));      \
    u64 prevQ = fma2(tM2M_Q, fM_Q, fma2(tI2M_Q, fI_Q, mul2(tD2M_Q, fD_Q)));      \
    float pUpLo = __shfl_up_sync(FULLMASK, f2lo(prevQ), 1, 16);                  \
    float pUpHi = __shfl_up_sync(FULLMASK, f2hi(prevQ), 1, 16);                  \
    if (sub == 0) pUpHi = fmaf(sM2M0, fM0, sI2M0 * fI0);                         \
    u64 fMnP = mul2(pk(ev.x, ev.y), pk(pUpHi, f2lo(prevP)));                     \
    u64 fMnQ = mul2(pk(ev.z, ev.w), pk(f2hi(prevP), f2lo(prevQ)));               \
    float fMnX = eselX * pUpLo; /* eX==0 at sub 0 -> fMn[0]=0 */                 \
    u64 fInP = fma2(tM2I_P, fM_P, mul2(tI2I_P, fI_P));                           \
    u64 fInQ = fma2(tM2I_Q, fM_Q, mul2(tI2I_Q, fI_Q));                           \
    float fI0n = fmaf(sM2I0, fM0, sI2I0 * fI0);                                  \
    float b1 = m0 * fMnX;                                                        \
    float b2 = fmaf(d1, b1, m1 * f2lo(fMnP));                                    \
    float b3 = fmaf(d2, b2, m2 * f2hi(fMnP));                                    \
    float Bc = fmaf(d3, b3, m3 * f2lo(fMnQ));                                    \
    float Bu;                                                                    \
    Bu = __shfl_up_sync(FULLMASK, Bc, 1, 16); if (sub >= 1) Bc = fmaf(Ak0, Bu, Bc); \
    Bu = __shfl_up_sync(FULLMASK, Bc, 2, 16); if (sub >= 2) Bc = fmaf(Ak1, Bu, Bc); \
    Bu = __shfl_up_sync(FULLMASK, Bc, 4, 16); if (sub >= 4) Bc = fmaf(Ak2, Bu, Bc); \
    Bu = __shfl_up_sync(FULLMASK, Bc, 8, 16); if (sub >= 8) Bc = fmaf(Ak3, Bu, Bc); \
    float fDp = __shfl_up_sync(FULLMASK, Bc, 1, 16);                             \
    if (sub == 0) fDp = 0.f;                                                     \
    fM_P = fMnP; fM_Q = fMnQ; fI_P = fInP; fI_Q = fInQ;                          \
    fI0 = fI0n; fM0 = 0.f;                                                       \
    fD_P = pk(fmaf(A1, fDp, b1), fmaf(A2, fDp, b2));                             \
    fD_Q = pk(fmaf(A3, fDp, b3), Bc);                                            \
} while (0)

#define PHMM_RESCALE do {                                                        \
    float m = fmaxf(fmaxf(f2lo(fM_P), f2hi(fM_P)), fmaxf(f2lo(fM_Q), f2hi(fM_Q))); \
    m = fmaxf(m, fmaxf(fmaxf(f2lo(fI_P), f2hi(fI_P)), fmaxf(f2lo(fI_Q), f2hi(fI_Q)))); \
    m = fmaxf(m, fmaxf(fmaxf(f2lo(fD_P), f2hi(fD_P)), fmaxf(f2lo(fD_Q), f2hi(fD_Q)))); \
    m = fmaxf(m, fI0);                                                           \
    m = fmaxf(m, __shfl_xor_sync(FULLMASK, m, 8, 16));                           \
    m = fmaxf(m, __shfl_xor_sync(FULLMASK, m, 4, 16));                           \
    m = fmaxf(m, __shfl_xor_sync(FULLMASK, m, 2, 16));                           \
    m = fmaxf(m, __shfl_xor_sync(FULLMASK, m, 1, 16));                           \
    int be = __float_as_int(m) >> 23;                                            \
    Ci += be - 127;                                                              \
    float r = __int_as_float((254 - be) << 23);                                  \
    u64 r2 = pk(r, r);                                                           \
    fM_P = mul2(fM_P, r2); fM_Q = mul2(fM_Q, r2);                                \
    fI_P = mul2(fI_P, r2); fI_Q = mul2(fI_Q, r2);                                \
    fD_P = mul2(fD_P, r2); fD_Q = mul2(fD_Q, r2);                                \
    fI0 *= r;                                                                    \
} while (0)

__global__ void __launch_bounds__(128, 6) phmm_fused_kernel(
    const int* __restrict__ xg, const float* __restrict__ ag,
    const float* __restrict__ eg, const float* __restrict__ mug,
    const float* __restrict__ lvg, float* __restrict__ outp)
{
    const int lane = threadIdx.x & 31;
    const int warp = threadIdx.x >> 5;        // 0..3
    const int sub  = lane & 15;               // lane within half-warp
    const int half = lane >> 4;
    const int eidx = (warp << 1) + half;      // element within block: 0..7
    const int b = (blockIdx.x << 3) + eidx;

    // per-element emission table: [4 syms][64 states] floats = 1KB
    __shared__ float etab[8 * 256];
    float* myt = etab + (eidx << 8);

    const float* ab  = ag + b * 455;     // (65,7)
    const float* ebp = eg + (b << 8);    // (64,4)

    const int R0 = sub << 2;
    const float* p0 = ab + R0 * 7;

    const float m0 = __expf(p0[2]),      d0 = __expf(p0[6]);
    const float m1 = __expf(p0[7 + 2]),  d1 = __expf(p0[7 + 6]);
    const float m2 = __expf(p0[14 + 2]), d2 = __expf(p0[14 + 6]);
    const float m3 = __expf(p0[21 + 2]), d3 = __expf(p0[21 + 6]);

    const u64 tM2M_P = pk(__expf(p0[7 + 0]), __expf(p0[14 + 0]));
    const u64 tM2I_P = pk(0.25f * __expf(p0[7 + 1]), 0.25f * __expf(p0[14 + 1]));
    const u64 tI2M_P = pk(__expf(p0[7 + 3]), __expf(p0[14 + 3]));
    const u64 tI2I_P = pk(0.25f * __expf(p0[7 + 4]), 0.25f * __expf(p0[14 + 4]));
    const u64 tD2M_P = pk(__expf(p0[7 + 5]), __expf(p0[14 + 5]));

    const u64 tM2M_Q = pk(__expf(p0[21 + 0]), __expf(p0[28 + 0]));
    const u64 tM2I_Q = pk(0.25f * __expf(p0[21 + 1]), 0.25f * __expf(p0[28 + 1]));
    const u64 tI2M_Q = pk(__expf(p0[21 + 3]), __expf(p0[28 + 3]));
    const u64 tI2I_Q = pk(0.25f * __expf(p0[21 + 4]), 0.25f * __expf(p0[28 + 4]));
    const u64 tD2M_Q = pk(__expf(p0[21 + 5]), __expf(p0[28 + 5]));

    // state-0 scalars
    const float sM2M0 = __expf(ab[0]);
    const float sM2I0 = 0.25f * __expf(ab[1]);
    const float sI2M0 = __expf(ab[3]);
    const float sI2I0 = 0.25f * __expf(ab[4]);

    // A-prefixes of the in-lane D-chain (loop-invariant)
    const float A1 = d0, A2 = d1 * d0, A3 = d2 * A2, Alane = d3 * A3;

    // emissions: rows 4s..4s+3 -> smem table [sym][state]
    float4 er0 = __ldg((const float4*)(ebp + (R0 << 2)));
    float4 er1 = __ldg((const float4*)(ebp + (R0 << 2) + 4));
    float4 er2 = __ldg((const float4*)(ebp + (R0 << 2) + 8));
    float4 er3 = __ldg((const float4*)(ebp + (R0 << 2) + 12));
    float x30 = __expf(er3.x), x31 = __expf(er3.y), x32 = __expf(er3.z), x33 = __expf(er3.w);
    myt[      R0] = __expf(er0.x); myt[ 64 + R0] = __expf(er0.y);
    myt[128 + R0] = __expf(er0.z); myt[192 + R0] = __expf(er0.w);
    myt[      R0 + 1] = __expf(er1.x); myt[ 64 + R0 + 1] = __expf(er1.y);
    myt[128 + R0 + 1] = __expf(er1.z); myt[192 + R0 + 1] = __expf(er1.w);
    myt[      R0 + 2] = __expf(er2.x); myt[ 64 + R0 + 2] = __expf(er2.y);
    myt[128 + R0 + 2] = __expf(er2.z); myt[192 + R0 + 2] = __expf(er2.w);
    myt[      R0 + 3] = x30; myt[ 64 + R0 + 3] = x31;
    myt[128 + R0 + 3] = x32; myt[192 + R0 + 3] = x33;
    // eX = e row 4s-1 (neighbor's row 4s+3), kept in registers
    float eX0 = __shfl_up_sync(FULLMASK, x30, 1, 16);
    float eX1 = __shfl_up_sync(FULLMASK, x31, 1, 16);
    float eX2 = __shfl_up_sync(FULLMASK, x32, 1, 16);
    float eX3 = __shfl_up_sync(FULLMASK, x33, 1, 16);
    if (sub == 0) { eX0 = 0.f; eX1 = 0.f; eX2 = 0.f; eX3 = 0.f; }
    __syncwarp();   // table visible to the owning half-warp

    // ---- pack symbols: lane sub loads x[8*sub..8*sub+7] (2 bits each = 16b),
    // one butterfly -> lanes 2m,2m+1 hold word m = symbols [16m..16m+15] ----
    int word;
    {
        const int4 xa = *(const int4*)(xg + (b << 7) + (sub << 3));
        const int4 xbv = *(const int4*)(xg + (b << 7) + (sub << 3) + 4);
        int c16 = xa.x | (xa.y << 2) | (xa.z << 4) | (xa.w << 6)
                | (xbv.x << 8) | (xbv.y << 10) | (xbv.z << 12) | (xbv.w << 14);
        int o1 = __shfl_xor_sync(FULLMASK, c16, 1, 16);
        word = (sub & 1) ? ((c16 << 16) | o1) : (c16 | (o1 << 16));
    }

    // Kogge-Stone A-side over 16 lanes
    float Ak0, Ak1, Ak2, Ak3;
    {
        float Ac = Alane;
        Ak0 = Ac;
        float Au = __shfl_up_sync(FULLMASK, Ac, 1, 16); if (sub >= 1) Ac *= Au;
        Ak1 = Ac;
        Au = __shfl_up_sync(FULLMASK, Ac, 2, 16);       if (sub >= 2) Ac *= Au;
        Ak2 = Ac;
        Au = __shfl_up_sync(FULLMASK, Ac, 4, 16);       if (sub >= 4) Ac *= Au;
        Ak3 = Ac;
    }

    // state (scaled linear space)
    u64 fM_P = pk(0.f, 0.f), fM_Q = pk(0.f, 0.f);
    u64 fI_P = pk(0.f, 0.f), fI_Q = pk(0.f, 0.f);
    u64 fD_P, fD_Q;
    float fM0 = 1.f, fI0 = 0.f;
    int Ci = 0;

    // initial D chain: fM_init[0]=1, rest 0
    {
        float b1 = (sub == 0) ? m0 : 0.f;
        float b2 = d1 * b1;
        float b3 = d2 * b2;
        float Bc = d3 * b3;
        float Bu;
        Bu = __shfl_up_sync(FULLMASK, Bc, 1, 16); if (sub >= 1) Bc = fmaf(Ak0, Bu, Bc);
        Bu = __shfl_up_sync(FULLMASK, Bc, 2, 16); if (sub >= 2) Bc = fmaf(Ak1, Bu, Bc);
        Bu = __shfl_up_sync(FULLMASK, Bc, 4, 16); if (sub >= 4) Bc = fmaf(Ak2, Bu, Bc);
        Bu = __shfl_up_sync(FULLMASK, Bc, 8, 16); if (sub >= 8) Bc = fmaf(Ak3, Bu, Bc);
        float fDp = __shfl_up_sync(FULLMASK, Bc, 1, 16);
        if (sub == 0) fDp = 0.f;
        fD_P = pk(fmaf(A1, fDp, b1), fmaf(A2, fDp, b2));
        fD_Q = pk(fmaf(A3, fDp, b3), Bc);
    }

    // ---- main loop: 8 words x 16 symbols; rescale every 8 steps ----
    #pragma unroll 1
    for (int wi = 0; wi < 8; ++wi) {
        int w = __shfl_sync(FULLMASK, word, wi << 1, 16);
        #pragma unroll
        for (int i = 0; i < 8; ++i) { PHMM_STEP(w & 3); w >>= 2; }
        PHMM_RESCALE;
        #pragma unroll
        for (int i = 0; i < 8; ++i) { PHMM_STEP(w & 3); w >>= 2; }
        PHMM_RESCALE;
    }

    // final = fM[64]*M2M[64] + fI[64]*I2M[64] + fD[64]*D2M[64] : sub=15, hi slot
    u64 fin2 = fma2(tM2M_Q, fM_Q, fma2(tI2M_Q, fI_Q, mul2(tD2M_Q, fD_Q)));
    float loss = -(__logf(f2hi(fin2)) + (float)Ci * 0.6931471805599453f);
    loss = __shfl_sync(FULLMASK, loss, 15, 16);   // broadcast within half

    // KLD: 16 values per element, one per lane of the half
    float mu = mug[(b << 4) + sub];
    float lv = lvg[(b << 4) + sub];
    float kt = 1.f + lv - mu * mu - __expf(lv);
    kt += __shfl_xor_sync(FULLMASK, kt, 8, 16);
    kt += __shfl_xor_sync(FULLMASK, kt, 4, 16);
    kt += __shfl_xor_sync(FULLMASK, kt, 2, 16);
    kt += __shfl_xor_sync(FULLMASK, kt, 1, 16);

    if (sub == 0) g_partial[b] = loss - 0.5f * kt;

    // ---- fused deterministic final reduction (last-block pattern) ----
    __shared__ float ws[4];
    __shared__ int isLast;
    __syncthreads();
    if (threadIdx.x == 0) {
        __threadfence();
        isLast = (atomicAdd(&g_count, 1) == (int)gridDim.x - 1);
    }
    __syncthreads();
    if (isLast) {
        const float4* gp = (const float4*)g_partial;
        float s = 0.f;
        #pragma unroll
        for (int i = 0; i < 8; ++i) {
            float4 v = gp[threadIdx.x + (i << 7)];
            s += (v.x + v.y) + (v.z + v.w);
        }
        s += __shfl_xor_sync(FULLMASK, s, 16);
        s += __shfl_xor_sync(FULLMASK, s, 8);
        s += __shfl_xor_sync(FULLMASK, s, 4);
        s += __shfl_xor_sync(FULLMASK, s, 2);
        s += __shfl_xor_sync(FULLMASK, s, 1);
        if (lane == 0) ws[warp] = s;
        __syncthreads();
        if (threadIdx.x == 0) {
            float t = ws[0] + ws[1] + ws[2] + ws[3];
            *outp = t * (1.0f / 4096.0f);
            g_count = 0;   // reset for next graph replay
        }
    }
}

extern "C" void kernel_launch(void* const* d_in, const int* in_sizes, int n_in,
                              void* d_out, int out_size)
{
    const int*   x   = (const int*)d_in[0];
    const float* a   = (const float*)d_in[1];
    const float* e   = (const float*)d_in[2];
    const float* mus = (const float*)d_in[3];
    const float* lvs = (const float*)d_in[4];

    phmm_fused_kernel<<<512, 128>>>(x, a, e, mus, lvs, (float*)d_out);
}

// round 15
// speedup vs baseline: 2.1019x; 1.1096x over previous
#include <cuda_runtime.h>

#define FULLMASK 0xFFFFFFFFu
typedef unsigned long long u64;

__device__ float g_partial[4096];
__device__ int g_count = 0;

// ---- f32x2 packed helpers (sm_100+) ----
static __device__ __forceinline__ u64 pk(float lo, float hi) {
    u64 r; asm("mov.b64 %0, {%1, %2};" : "=l"(r) : "f"(lo), "f"(hi)); return r;
}
static __device__ __forceinline__ float f2lo(u64 v) {
    float a, b; asm("mov.b64 {%0, %1}, %2;" : "=f"(a), "=f"(b) : "l"(v)); return a;
}
static __device__ __forceinline__ float f2hi(u64 v) {
    float a, b; asm("mov.b64 {%0, %1}, %2;" : "=f"(a), "=f"(b) : "l"(v)); return b;
}
static __device__ __forceinline__ u64 fma2(u64 a, u64 b, u64 c) {
    u64 d; asm("fma.rn.f32x2 %0, %1, %2, %3;" : "=l"(d) : "l"(a), "l"(b), "l"(c)); return d;
}
static __device__ __forceinline__ u64 mul2(u64 a, u64 b) {
    u64 d; asm("mul.rn.f32x2 %0, %1, %2;" : "=l"(d) : "l"(a), "l"(b)); return d;
}

// One step, fully branchless. Half-warp per element; lane sub owns states
// 4s+1..4s+4. Scan guards are folded into zeroed per-lane coefficients
// (Ak_i = 0 for sub < 2^i; A1..A3 = 0 at sub==0), so every FMA is
// unconditional — no BSSY/BSYNC on the critical path.
#define PHMM_STEP(XL) do {                                                       \
    const int xl = (XL);                                                         \
    const float4 ev = *(const float4*)(myt + ((xl) << 6) + (sub << 2));          \
    const bool s0 = (xl & 1) != 0, s1 = (xl & 2) != 0;                           \
    float eselX = s1 ? (s0 ? eX3 : eX2) : (s0 ? eX1 : eX0);                      \
    u64 prevP = fma2(tM2M_P, fM_P, fma2(tI2M_P, fI_P, mul2(tD2M_P, fD_P)));      \
    u64 prevQ = fma2(tM2M_Q, fM_Q, fma2(tI2M_Q, fI_Q, mul2(tD2M_Q, fD_Q)));      \
    float pUpLo = __shfl_up_sync(FULLMASK, f2lo(prevQ), 1, 16);                  \
    float pUpHi = __shfl_up_sync(FULLMASK, f2hi(prevQ), 1, 16);                  \
    float base0 = fmaf(sM2M0, fM0, sI2M0 * fI0);                                 \
    pUpHi = isSub0 ? base0 : pUpHi;                                              \
    u64 fMnP = mul2(pk(ev.x, ev.y), pk(pUpHi, f2lo(prevP)));                     \
    u64 fMnQ = mul2(pk(ev.z, ev.w), pk(f2hi(prevP), f2lo(prevQ)));               \
    float fMnX = eselX * pUpLo; /* eX==0 at sub 0 -> fMn[0]=0 */                 \
    u64 fInP = fma2(tM2I_P, fM_P, mul2(tI2I_P, fI_P));                           \
    u64 fInQ = fma2(tM2I_Q, fM_Q, mul2(tI2I_Q, fI_Q));                           \
    float fI0n = fmaf(sM2I0, fM0, sI2I0 * fI0);                                  \
    float b1 = m0 * fMnX;                                                        \
    float b2 = fmaf(d1, b1, m1 * f2lo(fMnP));                                    \
    float b3 = fmaf(d2, b2, m2 * f2hi(fMnP));                                    \
    float Bc = fmaf(d3, b3, m3 * f2lo(fMnQ));                                    \
    float Bu;                                                                    \
    Bu = __shfl_up_sync(FULLMASK, Bc, 1, 16); Bc = fmaf(Ak0, Bu, Bc);            \
    Bu = __shfl_up_sync(FULLMASK, Bc, 2, 16); Bc = fmaf(Ak1, Bu, Bc);            \
    Bu = __shfl_up_sync(FULLMASK, Bc, 4, 16); Bc = fmaf(Ak2, Bu, Bc);            \
    Bu = __shfl_up_sync(FULLMASK, Bc, 8, 16); Bc = fmaf(Ak3, Bu, Bc);            \
    float fDp = __shfl_up_sync(FULLMASK, Bc, 1, 16);                             \
    fM_P = fMnP; fM_Q = fMnQ; fI_P = fInP; fI_Q = fInQ;                          \
    fI0 = fI0n; fM0 = 0.f;                                                       \
    fD_P = pk(fmaf(A1, fDp, b1), fmaf(A2, fDp, b2));                             \
    fD_Q = pk(fmaf(A3, fDp, b3), Bc);                                            \
} while (0)

#define PHMM_RESCALE do {                                                        \
    float m = fmaxf(fmaxf(f2lo(fM_P), f2hi(fM_P)), fmaxf(f2lo(fM_Q), f2hi(fM_Q))); \
    m = fmaxf(m, fmaxf(fmaxf(f2lo(fI_P), f2hi(fI_P)), fmaxf(f2lo(fI_Q), f2hi(fI_Q)))); \
    m = fmaxf(m, fmaxf(fmaxf(f2lo(fD_P), f2hi(fD_P)), fmaxf(f2lo(fD_Q), f2hi(fD_Q)))); \
    m = fmaxf(m, fI0);                                                           \
    m = fmaxf(m, __shfl_xor_sync(FULLMASK, m, 8, 16));                           \
    m = fmaxf(m, __shfl_xor_sync(FULLMASK, m, 4, 16));                           \
    m = fmaxf(m, __shfl_xor_sync(FULLMASK, m, 2, 16));                           \
    m = fmaxf(m, __shfl_xor_sync(FULLMASK, m, 1, 16));                           \
    int be = __float_as_int(m) >> 23;                                            \
    Ci += be - 127;                                                              \
    float r = __int_as_float((254 - be) << 23);                                  \
    u64 r2 = pk(r, r);                                                           \
    fM_P = mul2(fM_P, r2); fM_Q = mul2(fM_Q, r2);                                \
    fI_P = mul2(fI_P, r2); fI_Q = mul2(fI_Q, r2);                                \
    fD_P = mul2(fD_P, r2); fD_Q = mul2(fD_Q, r2);                                \
    fI0 *= r;                                                                    \
} while (0)

__global__ void __launch_bounds__(128, 6) phmm_fused_kernel(
    const int* __restrict__ xg, const float* __restrict__ ag,
    const float* __restrict__ eg, const float* __restrict__ mug,
    const float* __restrict__ lvg, float* __restrict__ outp)
{
    const int lane = threadIdx.x & 31;
    const int warp = threadIdx.x >> 5;        // 0..3
    const int sub  = lane & 15;               // lane within half-warp
    const int half = lane >> 4;
    const int eidx = (warp << 1) + half;      // element within block: 0..7
    const int b = (blockIdx.x << 3) + eidx;
    const bool isSub0 = (sub == 0);

    // per-element emission table: [4 syms][64 states] floats = 1KB
    __shared__ float etab[8 * 256];
    float* myt = etab + (eidx << 8);

    const float* ab  = ag + b * 455;     // (65,7)
    const float* ebp = eg + (b << 8);    // (64,4)

    const int R0 = sub << 2;
    const float* p0 = ab + R0 * 7;

    const float m0 = __expf(p0[2]),      d0 = __expf(p0[6]);
    const float m1 = __expf(p0[7 + 2]),  d1 = __expf(p0[7 + 6]);
    const float m2 = __expf(p0[14 + 2]), d2 = __expf(p0[14 + 6]);
    const float m3 = __expf(p0[21 + 2]), d3 = __expf(p0[21 + 6]);

    const u64 tM2M_P = pk(__expf(p0[7 + 0]), __expf(p0[14 + 0]));
    const u64 tM2I_P = pk(0.25f * __expf(p0[7 + 1]), 0.25f * __expf(p0[14 + 1]));
    const u64 tI2M_P = pk(__expf(p0[7 + 3]), __expf(p0[14 + 3]));
    const u64 tI2I_P = pk(0.25f * __expf(p0[7 + 4]), 0.25f * __expf(p0[14 + 4]));
    const u64 tD2M_P = pk(__expf(p0[7 + 5]), __expf(p0[14 + 5]));

    const u64 tM2M_Q = pk(__expf(p0[21 + 0]), __expf(p0[28 + 0]));
    const u64 tM2I_Q = pk(0.25f * __expf(p0[21 + 1]), 0.25f * __expf(p0[28 + 1]));
    const u64 tI2M_Q = pk(__expf(p0[21 + 3]), __expf(p0[28 + 3]));
    const u64 tI2I_Q = pk(0.25f * __expf(p0[21 + 4]), 0.25f * __expf(p0[28 + 4]));
    const u64 tD2M_Q = pk(__expf(p0[21 + 5]), __expf(p0[28 + 5]));

    // state-0 scalars
    const float sM2M0 = __expf(ab[0]);
    const float sM2I0 = 0.25f * __expf(ab[1]);
    const float sI2M0 = __expf(ab[3]);
    const float sI2I0 = 0.25f * __expf(ab[4]);

    // In-lane D-chain A-prefixes. Alane is the raw full product (for the scan
    // coefficients); A1..A3 are ZEROED at sub==0 so the fDp contribution
    // vanishes there without a branch or select.
    const float Alane = d3 * d2 * d1 * d0;
    const float edge = isSub0 ? 0.f : 1.f;
    const float A1 = d0 * edge, A2 = d1 * d0 * edge, A3 = d2 * d1 * d0 * edge;

    // emissions: rows 4s..4s+3 -> smem table [sym][state]
    float4 er0 = __ldg((const float4*)(ebp + (R0 << 2)));
    float4 er1 = __ldg((const float4*)(ebp + (R0 << 2) + 4));
    float4 er2 = __ldg((const float4*)(ebp + (R0 << 2) + 8));
    float4 er3 = __ldg((const float4*)(ebp + (R0 << 2) + 12));
    float x30 = __expf(er3.x), x31 = __expf(er3.y), x32 = __expf(er3.z), x33 = __expf(er3.w);
    myt[      R0] = __expf(er0.x); myt[ 64 + R0] = __expf(er0.y);
    myt[128 + R0] = __expf(er0.z); myt[192 + R0] = __expf(er0.w);
    myt[      R0 + 1] = __expf(er1.x); myt[ 64 + R0 + 1] = __expf(er1.y);
    myt[128 + R0 + 1] = __expf(er1.z); myt[192 + R0 + 1] = __expf(er1.w);
    myt[      R0 + 2] = __expf(er2.x); myt[ 64 + R0 + 2] = __expf(er2.y);
    myt[128 + R0 + 2] = __expf(er2.z); myt[192 + R0 + 2] = __expf(er2.w);
    myt[      R0 + 3] = x30; myt[ 64 + R0 + 3] = x31;
    myt[128 + R0 + 3] = x32; myt[192 + R0 + 3] = x33;
    // eX = e row 4s-1 (neighbor's row 4s+3); zeroed at sub==0
    float eX0 = __shfl_up_sync(FULLMASK, x30, 1, 16) * edge;
    float eX1 = __shfl_up_sync(FULLMASK, x31, 1, 16) * edge;
    float eX2 = __shfl_up_sync(FULLMASK, x32, 1, 16) * edge;
    float eX3 = __shfl_up_sync(FULLMASK, x33, 1, 16) * edge;
    __syncwarp();   // table visible to the owning half-warp

    // ---- pack symbols: lane sub loads x[8*sub..8*sub+7] (2 bits each = 16b),
    // one butterfly -> lanes 2m,2m+1 hold word m = symbols [16m..16m+15] ----
    int word;
    {
        const int4 xa = *(const int4*)(xg + (b << 7) + (sub << 3));
        const int4 xbv = *(const int4*)(xg + (b << 7) + (sub << 3) + 4);
        int c16 = xa.x | (xa.y << 2) | (xa.z << 4) | (xa.w << 6)
                | (xbv.x << 8) | (xbv.y << 10) | (xbv.z << 12) | (xbv.w << 14);
        int o1 = __shfl_xor_sync(FULLMASK, c16, 1, 16);
        word = (sub & 1) ? ((c16 << 16) | o1) : (c16 | (o1 << 16));
    }

    // Kogge-Stone A-side over 16 lanes; coefficients ZEROED below each
    // level's horizon so the in-loop scan FMAs need no guards.
    float Ak0, Ak1, Ak2, Ak3;
    {
        float Ac = Alane;
        Ak0 = (sub >= 1) ? Ac : 0.f;
        float Au = __shfl_up_sync(FULLMASK, Ac, 1, 16);
        Ac *= (sub >= 1) ? Au : 1.f;
        Ak1 = (sub >= 2) ? Ac : 0.f;
        Au = __shfl_up_sync(FULLMASK, Ac, 2, 16);
        Ac *= (sub >= 2) ? Au : 1.f;
        Ak2 = (sub >= 4) ? Ac : 0.f;
        Au = __shfl_up_sync(FULLMASK, Ac, 4, 16);
        Ac *= (sub >= 4) ? Au : 1.f;
        Ak3 = (sub >= 8) ? Ac : 0.f;
    }

    // state (scaled linear space)
    u64 fM_P = pk(0.f, 0.f), fM_Q = pk(0.f, 0.f);
    u64 fI_P = pk(0.f, 0.f), fI_Q = pk(0.f, 0.f);
    u64 fD_P, fD_Q;
    float fM0 = 1.f, fI0 = 0.f;
    int Ci = 0;

    // initial D chain: fM_init[0]=1, rest 0 (branchless)
    {
        float b1 = isSub0 ? m0 : 0.f;
        float b2 = d1 * b1;
        float b3 = d2 * b2;
        float Bc = d3 * b3;
        float Bu;
        Bu = __shfl_up_sync(FULLMASK, Bc, 1, 16); Bc = fmaf(Ak0, Bu, Bc);
        Bu = __shfl_up_sync(FULLMASK, Bc, 2, 16); Bc = fmaf(Ak1, Bu, Bc);
        Bu = __shfl_up_sync(FULLMASK, Bc, 4, 16); Bc = fmaf(Ak2, Bu, Bc);
        Bu = __shfl_up_sync(FULLMASK, Bc, 8, 16); Bc = fmaf(Ak3, Bu, Bc);
        float fDp = __shfl_up_sync(FULLMASK, Bc, 1, 16);
        fD_P = pk(fmaf(A1, fDp, b1), fmaf(A2, fDp, b2));
        fD_Q = pk(fmaf(A3, fDp, b3), Bc);
    }

    // ---- main loop: 8 words x 16 symbols; rescale every 8 steps ----
    #pragma unroll 1
    for (int wi = 0; wi < 8; ++wi) {
        int w = __shfl_sync(FULLMASK, word, wi << 1, 16);
        #pragma unroll
        for (int i = 0; i < 8; ++i) { PHMM_STEP(w & 3); w >>= 2; }
        PHMM_RESCALE;
        #pragma unroll
        for (int i = 0; i < 8; ++i) { PHMM_STEP(w & 3); w >>= 2; }
        PHMM_RESCALE;
    }

    // final = fM[64]*M2M[64] + fI[64]*I2M[64] + fD[64]*D2M[64] : sub=15, hi slot
    u64 fin2 = fma2(tM2M_Q, fM_Q, fma2(tI2M_Q, fI_Q, mul2(tD2M_Q, fD_Q)));
    float loss = -(__logf(f2hi(fin2)) + (float)Ci * 0.6931471805599453f);
    loss = __shfl_sync(FULLMASK, loss, 15, 16);   // broadcast within half

    // KLD: 16 values per element, one per lane of the half
    float mu = mug[(b << 4) + sub];
    float lv = lvg[(b << 4) + sub];
    float kt = 1.f + lv - mu * mu - __expf(lv);
    kt += __shfl_xor_sync(FULLMASK, kt, 8, 16);
    kt += __shfl_xor_sync(FULLMASK, kt, 4, 16);
    kt += __shfl_xor_sync(FULLMASK, kt, 2, 16);
    kt += __shfl_xor_sync(FULLMASK, kt, 1, 16);

    if (sub == 0) g_partial[b] = loss - 0.5f * kt;

    // ---- fused deterministic final reduction (last-block pattern) ----
    __shared__ float ws[4];
    __shared__ int isLast;
    __syncthreads();
    if (threadIdx.x == 0) {
        __threadfence();
        isLast = (atomicAdd(&g_count, 1) == (int)gridDim.x - 1);
    }
    __syncthreads();
    if (isLast) {
        const float4* gp = (const float4*)g_partial;
        float s = 0.f;
        #pragma unroll
        for (int i = 0; i < 8; ++i) {
            float4 v = gp[threadIdx.x + (i << 7)];
            s += (v.x + v.y) + (v.z + v.w);
        }
        s += __shfl_xor_sync(FULLMASK, s, 16);
        s += __shfl_xor_sync(FULLMASK, s, 8);
        s += __shfl_xor_sync(FULLMASK, s, 4);
        s += __shfl_xor_sync(FULLMASK, s, 2);
        s += __shfl_xor_sync(FULLMASK, s, 1);
        if (lane == 0) ws[warp] = s;
        __syncthreads();
        if (threadIdx.x == 0) {
            float t = ws[0] + ws[1] + ws[2] + ws[3];
            *outp = t * (1.0f / 4096.0f);
            g_count = 0;   // reset for next graph replay
        }
    }
}

extern "C" void kernel_launch(void* const* d_in, const int* in_sizes, int n_in,
                              void* d_out, int out_size)
{
    const int*   x   = (const int*)d_in[0];
    const float* a   = (const float*)d_in[1];
    const float* e   = (const float*)d_in[2];
    const float* mus = (const float*)d_in[3];
    const float* lvs = (const float*)d_in[4];

    phmm_fused_kernel<<<512, 128>>>(x, a, e, mus, lvs, (float*)d_out);
}